// round 3
// baseline (speedup 1.0000x reference)
#include <cuda_runtime.h>
#include <cuda_bf16.h>
#include <math.h>

// Shapes: B=1, S=128, L=256, D=768 (H=12, dh=64), M = S*L = 32768, 3D = 2304.
#define SQ   128
#define LQ   256
#define DQ   768
#define HQ   12
#define DHQ  64
#define MQ   (SQ * LQ)      // 32768
#define N3Q  (3 * DQ)       // 2304

// ---------------- scratch (no cudaMalloc allowed) ----------------
__device__ float g_qkv[(size_t)MQ * N3Q];       // 302 MB, reused for row & col stage
__device__ float g_attn[HQ * LQ * LQ];          // 3 MB   row-attention logits/probs
__device__ float g_tmp[(size_t)MQ * DQ];        // 100 MB attention outputs (row then col)
__device__ float g_out1[(size_t)MQ * DQ];       // 100 MB output of first residual+LN

// =================================================================
// Kernel 1: C[M,N] = A[M,K] * B[N,K]^T + bias[N]   (both K-major, NT)
// 128x128 tile, BK=16, 256 threads, 8x8 per thread, reg prefetch.
// =================================================================
__global__ __launch_bounds__(256) void sgemm_nt_bias(
    const float* __restrict__ A, const float* __restrict__ B,
    const float* __restrict__ bias, float* __restrict__ C,
    int M, int N, int K)
{
    __shared__ float As[16][132];
    __shared__ float Bs[16][132];
    const int tid = threadIdx.x;
    const int bm = blockIdx.y * 128;
    const int bn = blockIdx.x * 128;
    const int lr = tid >> 2;          // 0..63
    const int lc = (tid & 3) << 2;    // 0,4,8,12
    const int tx = tid & 15;
    const int ty = tid >> 4;

    const float* Ap = A + (size_t)(bm + lr) * K + lc;
    const float* Bp = B + (size_t)(bn + lr) * K + lc;

    float4 pa0 = *(const float4*)Ap;
    float4 pa1 = *(const float4*)(Ap + (size_t)64 * K);
    float4 pb0 = *(const float4*)Bp;
    float4 pb1 = *(const float4*)(Bp + (size_t)64 * K);

    float acc[8][8];
#pragma unroll
    for (int i = 0; i < 8; i++)
#pragma unroll
        for (int j = 0; j < 8; j++) acc[i][j] = 0.f;

    const int nk = K >> 4;
    for (int kt = 0; kt < nk; kt++) {
        As[lc + 0][lr]      = pa0.x; As[lc + 1][lr]      = pa0.y;
        As[lc + 2][lr]      = pa0.z; As[lc + 3][lr]      = pa0.w;
        As[lc + 0][lr + 64] = pa1.x; As[lc + 1][lr + 64] = pa1.y;
        As[lc + 2][lr + 64] = pa1.z; As[lc + 3][lr + 64] = pa1.w;
        Bs[lc + 0][lr]      = pb0.x; Bs[lc + 1][lr]      = pb0.y;
        Bs[lc + 2][lr]      = pb0.z; Bs[lc + 3][lr]      = pb0.w;
        Bs[lc + 0][lr + 64] = pb1.x; Bs[lc + 1][lr + 64] = pb1.y;
        Bs[lc + 2][lr + 64] = pb1.z; Bs[lc + 3][lr + 64] = pb1.w;
        __syncthreads();

        if (kt + 1 < nk) {
            Ap += 16; Bp += 16;
            pa0 = *(const float4*)Ap;
            pa1 = *(const float4*)(Ap + (size_t)64 * K);
            pb0 = *(const float4*)Bp;
            pb1 = *(const float4*)(Bp + (size_t)64 * K);
        }

#pragma unroll
        for (int k = 0; k < 16; k++) {
            float a[8], b[8];
            *(float4*)(a)     = *(const float4*)(&As[k][ty * 4]);
            *(float4*)(a + 4) = *(const float4*)(&As[k][ty * 4 + 64]);
            *(float4*)(b)     = *(const float4*)(&Bs[k][tx * 4]);
            *(float4*)(b + 4) = *(const float4*)(&Bs[k][tx * 4 + 64]);
#pragma unroll
            for (int i = 0; i < 8; i++)
#pragma unroll
                for (int j = 0; j < 8; j++)
                    acc[i][j] += a[i] * b[j];
        }
        __syncthreads();
    }

    float bv[8];
    *(float4*)(bv)     = *(const float4*)(bias + bn + tx * 4);
    *(float4*)(bv + 4) = *(const float4*)(bias + bn + tx * 4 + 64);
#pragma unroll
    for (int i = 0; i < 8; i++) {
        int m = bm + ((i < 4) ? (ty * 4 + i) : (ty * 4 + 60 + i));
        float4 o0 = make_float4(acc[i][0] + bv[0], acc[i][1] + bv[1],
                                acc[i][2] + bv[2], acc[i][3] + bv[3]);
        float4 o1 = make_float4(acc[i][4] + bv[4], acc[i][5] + bv[5],
                                acc[i][6] + bv[6], acc[i][7] + bv[7]);
        float* cp = C + (size_t)m * N + bn + tx * 4;
        *(float4*)cp        = o0;
        *(float4*)(cp + 64) = o1;
    }
}

// =================================================================
// Kernel 2: row logits   attn[h,i,j] = sum_{s,c} Q[s,i,h,c] K[s,j,h,c]
// 64x64 tile per CTA, 256 threads (16x16), 4x4 per thread, loop s.
// =================================================================
__global__ __launch_bounds__(256) void row_logits(
    const float* __restrict__ qkv, float* __restrict__ attn)
{
    __shared__ float Qs[64][65];
    __shared__ float Ks[64][65];
    const int h  = blockIdx.z;
    const int i0 = blockIdx.y * 64;
    const int j0 = blockIdx.x * 64;
    const int tid  = threadIdx.x;
    const int lrow = tid >> 2;            // 0..63
    const int lcol = (tid & 3) << 4;      // 0,16,32,48
    const int tx = tid & 15;
    const int ty = tid >> 4;
    const int hb = h * DHQ;

    float acc[4][4];
#pragma unroll
    for (int i = 0; i < 4; i++)
#pragma unroll
        for (int j = 0; j < 4; j++) acc[i][j] = 0.f;

    for (int s = 0; s < SQ; s++) {
        const float* qrow = qkv + (size_t)(s * LQ + i0 + lrow) * N3Q + hb + lcol;
        const float* krow = qkv + (size_t)(s * LQ + j0 + lrow) * N3Q + DQ + hb + lcol;
#pragma unroll
        for (int u = 0; u < 16; u += 4) {
            float4 qa = *(const float4*)(qrow + u);
            Qs[lrow][lcol + u + 0] = qa.x; Qs[lrow][lcol + u + 1] = qa.y;
            Qs[lrow][lcol + u + 2] = qa.z; Qs[lrow][lcol + u + 3] = qa.w;
            float4 ka = *(const float4*)(krow + u);
            Ks[lrow][lcol + u + 0] = ka.x; Ks[lrow][lcol + u + 1] = ka.y;
            Ks[lrow][lcol + u + 2] = ka.z; Ks[lrow][lcol + u + 3] = ka.w;
        }
        __syncthreads();
#pragma unroll 16
        for (int c = 0; c < DHQ; c++) {
            float a[4], b[4];
#pragma unroll
            for (int r = 0; r < 4; r++) a[r] = Qs[ty * 4 + r][c];
#pragma unroll
            for (int r = 0; r < 4; r++) b[r] = Ks[tx * 4 + r][c];
#pragma unroll
            for (int i = 0; i < 4; i++)
#pragma unroll
                for (int j = 0; j < 4; j++)
                    acc[i][j] += a[i] * b[j];
        }
        __syncthreads();
    }
#pragma unroll
    for (int i = 0; i < 4; i++) {
        float4 v = make_float4(acc[i][0], acc[i][1], acc[i][2], acc[i][3]);
        *(float4*)&attn[(size_t)h * LQ * LQ + (i0 + ty * 4 + i) * LQ + j0 + tx * 4] = v;
    }
}

// =================================================================
// Kernel 3: softmax over last dim (256) of attn[h,i,:]
// =================================================================
__global__ __launch_bounds__(256) void softmax_row(float* __restrict__ attn)
{
    const int row = blockIdx.x;          // h*256 + i
    float* p = attn + (size_t)row * LQ;
    const int t = threadIdx.x;
    float v = p[t];

    __shared__ float red[8];
    float m = v;
#pragma unroll
    for (int o = 16; o > 0; o >>= 1) m = fmaxf(m, __shfl_xor_sync(0xffffffffu, m, o));
    if ((t & 31) == 0) red[t >> 5] = m;
    __syncthreads();
    float mm = red[0];
#pragma unroll
    for (int k = 1; k < 8; k++) mm = fmaxf(mm, red[k]);
    __syncthreads();

    float e = expf(v - mm);
    float s = e;
#pragma unroll
    for (int o = 16; o > 0; o >>= 1) s += __shfl_xor_sync(0xffffffffu, s, o);
    if ((t & 31) == 0) red[t >> 5] = s;
    __syncthreads();
    float tot = 0.f;
#pragma unroll
    for (int k = 0; k < 8; k++) tot += red[k];

    p[t] = e / tot;
}

// =================================================================
// Kernel 4: row AV  out[s,i,h,d] = sum_j attn[h,i,j] V[s,j,h,d]
// per CTA: one (s,h), 64 i x 64 d, j in chunks of 32.
// =================================================================
__global__ __launch_bounds__(256) void row_av(
    const float* __restrict__ attn, const float* __restrict__ qkv,
    float* __restrict__ out)
{
    __shared__ float As[64][36];
    __shared__ float Vs[32][68];
    const int i0 = blockIdx.x * 64;
    const int h  = blockIdx.y;
    const int s  = blockIdx.z;
    const int tid = threadIdx.x;
    const int tx = tid & 15, ty = tid >> 4;
    const int a_row = tid >> 2, a_col = (tid & 3) << 3;   // 64 x 32 tile
    const int v_row = tid >> 3, v_col = (tid & 7) << 3;   // 32 x 64 tile

    float acc[4][4];
#pragma unroll
    for (int i = 0; i < 4; i++)
#pragma unroll
        for (int j = 0; j < 4; j++) acc[i][j] = 0.f;

    for (int jb = 0; jb < LQ; jb += 32) {
        const float* ap = attn + (size_t)h * LQ * LQ + (i0 + a_row) * LQ + jb + a_col;
        *(float4*)&As[a_row][a_col]     = *(const float4*)ap;
        *(float4*)&As[a_row][a_col + 4] = *(const float4*)(ap + 4);
        const float* vp = qkv + (size_t)(s * LQ + jb + v_row) * N3Q + 2 * DQ + h * DHQ + v_col;
        *(float4*)&Vs[v_row][v_col]     = *(const float4*)vp;
        *(float4*)&Vs[v_row][v_col + 4] = *(const float4*)(vp + 4);
        __syncthreads();
#pragma unroll 16
        for (int j = 0; j < 32; j++) {
            float a[4], v[4];
#pragma unroll
            for (int r = 0; r < 4; r++) a[r] = As[ty * 4 + r][j];
#pragma unroll
            for (int r = 0; r < 4; r++) v[r] = Vs[j][tx * 4 + r];
#pragma unroll
            for (int i = 0; i < 4; i++)
#pragma unroll
                for (int d = 0; d < 4; d++)
                    acc[i][d] += a[i] * v[d];
        }
        __syncthreads();
    }
#pragma unroll
    for (int i = 0; i < 4; i++) {
        float4 v = make_float4(acc[i][0], acc[i][1], acc[i][2], acc[i][3]);
        *(float4*)&out[(size_t)(s * LQ + i0 + ty * 4 + i) * DQ + h * DHQ + tx * 4] = v;
    }
}

// =================================================================
// Kernel 5: out[row,:] = LN(X[row,:] + R[row,:]) * g + b   (D=768)
// =================================================================
__global__ __launch_bounds__(256) void add_ln(
    const float* __restrict__ X, const float* __restrict__ R,
    const float* __restrict__ g, const float* __restrict__ b,
    float* __restrict__ out)
{
    const int row = blockIdx.x;
    const int t = threadIdx.x;
    const float* x = X + (size_t)row * DQ;
    const float* r = R + (size_t)row * DQ;
    float y0 = x[t]       + r[t];
    float y1 = x[t + 256] + r[t + 256];
    float y2 = x[t + 512] + r[t + 512];
    float s = y0 + y1 + y2;
    float q = y0 * y0 + y1 * y1 + y2 * y2;

    __shared__ float ss[8], qq[8];
#pragma unroll
    for (int o = 16; o > 0; o >>= 1) {
        s += __shfl_xor_sync(0xffffffffu, s, o);
        q += __shfl_xor_sync(0xffffffffu, q, o);
    }
    if ((t & 31) == 0) { ss[t >> 5] = s; qq[t >> 5] = q; }
    __syncthreads();
    if (t < 32) {
        float s2 = (t < 8) ? ss[t] : 0.f;
        float q2 = (t < 8) ? qq[t] : 0.f;
#pragma unroll
        for (int o = 4; o > 0; o >>= 1) {
            s2 += __shfl_xor_sync(0xffffffffu, s2, o);
            q2 += __shfl_xor_sync(0xffffffffu, q2, o);
        }
        if (t == 0) { ss[0] = s2; qq[0] = q2; }
    }
    __syncthreads();
    const float invD = 1.f / (float)DQ;
    float mean = ss[0] * invD;
    float var  = qq[0] * invD - mean * mean;
    float inv  = rsqrtf(var + 1e-5f);
    float* o = out + (size_t)row * DQ;
    o[t]       = (y0 - mean) * inv * g[t]       + b[t];
    o[t + 256] = (y1 - mean) * inv * g[t + 256] + b[t + 256];
    o[t + 512] = (y2 - mean) * inv * g[t + 512] + b[t + 512];
}

// =================================================================
// Kernel 7: column attention. One CTA per (l,h); 128 threads; thread i
// owns query i. S=128, dh=64. Standard attention over j.
// smem: P[j][i] 64KB + Kt[c][j] 32KB + Vt[d][j] 32KB = 128KB dynamic.
// =================================================================
__global__ __launch_bounds__(128) void col_attn_kernel(
    const float* __restrict__ qkv, float* __restrict__ out)
{
    extern __shared__ float sm[];
    float* P  = sm;                 // [128*128] transposed: P[j*128 + i]
    float* Kt = sm + 128 * 128;     // [64*128]  Kt[c*128 + j]
    float* Vt = Kt + 64 * 128;      // [64*128]  Vt[d*128 + j]

    const int l = blockIdx.x;
    const int h = blockIdx.y;
    const int t = threadIdx.x;      // = i, and loader row j
    const int base = l * N3Q + h * DHQ;

    // load K,V row t (coalesced per-thread rows; conflict-free smem stores)
    const float* krow = qkv + (size_t)(t * LQ) * N3Q + base + DQ;
    const float* vrow = krow + DQ;
#pragma unroll
    for (int c = 0; c < DHQ; c += 4) {
        float4 kv = *(const float4*)(krow + c);
        Kt[(c + 0) * 128 + t] = kv.x; Kt[(c + 1) * 128 + t] = kv.y;
        Kt[(c + 2) * 128 + t] = kv.z; Kt[(c + 3) * 128 + t] = kv.w;
        float4 vv = *(const float4*)(vrow + c);
        Vt[(c + 0) * 128 + t] = vv.x; Vt[(c + 1) * 128 + t] = vv.y;
        Vt[(c + 2) * 128 + t] = vv.z; Vt[(c + 3) * 128 + t] = vv.w;
    }
    float q[DHQ];
    const float* qrow = qkv + (size_t)(t * LQ) * N3Q + base;
#pragma unroll
    for (int c = 0; c < DHQ; c += 4) {
        float4 qv = *(const float4*)(qrow + c);
        q[c] = qv.x; q[c + 1] = qv.y; q[c + 2] = qv.z; q[c + 3] = qv.w;
    }
    __syncthreads();

    // logits: P[j][t] = q_t . k_j
    for (int j = 0; j < SQ; j++) {
        float a0 = 0.f, a1 = 0.f, a2 = 0.f, a3 = 0.f;
#pragma unroll
        for (int c = 0; c < DHQ; c += 4) {
            a0 += q[c]     * Kt[(c)     * 128 + j];
            a1 += q[c + 1] * Kt[(c + 1) * 128 + j];
            a2 += q[c + 2] * Kt[(c + 2) * 128 + j];
            a3 += q[c + 3] * Kt[(c + 3) * 128 + j];
        }
        P[j * 128 + t] = (a0 + a1) + (a2 + a3);
    }

    // private softmax over j for query t
    float m = -3.4e38f;
    for (int j = 0; j < SQ; j++) m = fmaxf(m, P[j * 128 + t]);
    float ssum = 0.f;
    for (int j = 0; j < SQ; j++) {
        float e = expf(P[j * 128 + t] - m);
        P[j * 128 + t] = e;
        ssum += e;
    }
    const float inv = 1.f / ssum;

    // O = P V
    float o[DHQ];
#pragma unroll
    for (int d = 0; d < DHQ; d++) o[d] = 0.f;
    for (int j = 0; j < SQ; j++) {
        float p = P[j * 128 + t];
#pragma unroll
        for (int d = 0; d < DHQ; d++) o[d] += p * Vt[d * 128 + j];
    }

    float* orow = out + (size_t)(t * LQ + l) * DQ + h * DHQ;
#pragma unroll
    for (int d = 0; d < DHQ; d += 4) {
        float4 v = make_float4(o[d] * inv, o[d + 1] * inv, o[d + 2] * inv, o[d + 3] * inv);
        *(float4*)(orow + d) = v;
    }
}

// =================================================================
extern "C" void kernel_launch(void* const* d_in, const int* in_sizes, int n_in,
                              void* d_out, int out_size)
{
    const float* x     = (const float*)d_in[0];
    const float* w_row = (const float*)d_in[1];
    const float* b_row = (const float*)d_in[2];
    const float* w_col = (const float*)d_in[3];
    const float* b_col = (const float*)d_in[4];
    const float* g1    = (const float*)d_in[5];
    const float* beta1 = (const float*)d_in[6];
    const float* g2    = (const float*)d_in[7];
    const float* beta2 = (const float*)d_in[8];
    float* out = (float*)d_out;

    float *qkv, *attn, *tmp, *out1;
    cudaGetSymbolAddress((void**)&qkv,  g_qkv);
    cudaGetSymbolAddress((void**)&attn, g_attn);
    cudaGetSymbolAddress((void**)&tmp,  g_tmp);
    cudaGetSymbolAddress((void**)&out1, g_out1);

    cudaFuncSetAttribute(col_attn_kernel,
                         cudaFuncAttributeMaxDynamicSharedMemorySize, 131072);

    dim3 gemm_grid(N3Q / 128, MQ / 128);   // (18, 256)

    // --- row stage ---
    sgemm_nt_bias<<<gemm_grid, 256>>>(x, w_row, b_row, qkv, MQ, N3Q, DQ);
    row_logits<<<dim3(4, 4, HQ), 256>>>(qkv, attn);
    softmax_row<<<HQ * LQ, 256>>>(attn);
    row_av<<<dim3(4, HQ, SQ), 256>>>(attn, qkv, tmp);
    add_ln<<<MQ, 256>>>(x, tmp, g1, beta1, out1);

    // --- column stage ---
    sgemm_nt_bias<<<gemm_grid, 256>>>(out1, w_col, b_col, qkv, MQ, N3Q, DQ);
    col_attn_kernel<<<dim3(LQ, HQ), 128, 131072>>>(qkv, tmp);
    add_ln<<<MQ, 256>>>(out1, tmp, g2, beta2, out);
}